// round 6
// baseline (speedup 1.0000x reference)
#include <cuda_runtime.h>

#define MARGIN  1.9f
#define GRID    592              // 4 blocks/SM on 148 SMs, all wave-1 resident
#define NMAXE   1024
#define BIGF    3.0e38f
#define BSCALE  8.0f             // 256 buckets over d in [0,32)

// Scratch (no allocation allowed)
__device__ float g_dotA[640 * 640];  // partial dots k in [0,64)
__device__ float g_dotB[640 * 640];  // partial dots k in [64,128)
__device__ float g_sq[NMAXE];
__device__ int   g_lab[NMAXE];
__device__ float g_bsum[GRID];
__device__ int   g_bcnt[GRID];
__device__ int   g_bval[GRID];
__device__ int   g_bar1 = 0;
__device__ int   g_bar2 = 0;

// Fused kernel, grid=592:
//  phase 1: blocks 0..199  : 64x64 dot tiles, k split in 2 halves (100 tiles x 2)
//           blocks 200..219: 32 row sq-norms each
//           block  220     : label normalization; 221..591 idle
//  grid barrier
//  phase 2: block b -> anchors i = b, b+592. Counting-sort histogram of the
//           negatives, prefix scans, O(1)+boundary query per positive.
//  phase 3: last block reduces partials -> out[4], resets barriers
__global__ void __launch_bounds__(256, 4)
fused_triplet_kernel(const float* __restrict__ e, const int* __restrict__ lab32,
                     float* __restrict__ out, int n) {
    __shared__ float As[64 * 68];    // 17.4 KB (phase 1)
    __shared__ float Bs[64 * 64];    // 16 KB   (phase 1)
    // phase 2 histogram structures (~7 KB extra; total < 57 KB for 4/SM)
    __shared__ int   hcnt[256];
    __shared__ int   pcs[257];       // exclusive prefix of counts; pcs[256]=Ntot
    __shared__ int   cur[256];       // scatter cursors
    __shared__ float pvs[256];       // exclusive prefix of per-bucket value sums
    __shared__ float bval[704];      // negatives grouped by bucket
    __shared__ int   swi[8], swi2[8];
    __shared__ float swf[8], swf2[8];
    __shared__ int   s_old, s_is64;
    __shared__ float wsum[8];
    __shared__ int   wcnt[8];

    const int b    = blockIdx.x;
    const int tid  = threadIdx.x;
    const int lane = tid & 31;
    const int wid  = tid >> 5;
    const float4* e4 = (const float4*)e;

    const int tiles_x     = n >> 6;                    // 10
    const int tiles       = tiles_x * tiles_x;         // 100
    const int dist_blocks = tiles * 2;                 // 200 (k split)
    const int sq_blocks   = n >> 5;                    // 20
    const int lab_block   = dist_blocks + sq_blocks;   // 220

    // ================= phase 1 =================
    if (b < dist_blocks) {
        const int ch = (b < tiles) ? 0 : 1;            // k half
        const int t  = (b < tiles) ? b : (b - tiles);
        const int ti = t / tiles_x;
        const int tj = t % tiles_x;
        const int tx = tid & 15;
        const int ty = tid >> 4;
        float* __restrict__ gout = ch ? g_dotB : g_dotA;

        float acc[4][4];
        #pragma unroll
        for (int q = 0; q < 4; q++)
            #pragma unroll
            for (int r = 0; r < 4; r++) acc[q][r] = 0.f;

        #pragma unroll
        for (int r = 0; r < 4; r++) {
            int lin = tid + r * 256;
            int row = lin >> 4;
            int c4  = lin & 15;
            float4 v = e4[(size_t)(ti * 64 + row) * 32 + ch * 16 + c4];
            *(float4*)&As[row * 68 + c4 * 4] = v;
        }
        #pragma unroll
        for (int r = 0; r < 4; r++) {
            int lin = tid + r * 256;
            int j   = lin & 63;
            int c4i = lin >> 6;
            float4 v = e4[(size_t)(tj * 64 + j) * 32 + ch * 16 + c4i];
            Bs[(c4i * 4 + 0) * 64 + j] = v.x;
            Bs[(c4i * 4 + 1) * 64 + j] = v.y;
            Bs[(c4i * 4 + 2) * 64 + j] = v.z;
            Bs[(c4i * 4 + 3) * 64 + j] = v.w;
        }
        __syncthreads();

        #pragma unroll 4
        for (int k = 0; k < 64; k++) {
            float4 bv = *(const float4*)&Bs[k * 64 + 4 * tx];
            float a0 = As[(4 * ty + 0) * 68 + k];
            float a1 = As[(4 * ty + 1) * 68 + k];
            float a2 = As[(4 * ty + 2) * 68 + k];
            float a3 = As[(4 * ty + 3) * 68 + k];
            acc[0][0] = fmaf(a0, bv.x, acc[0][0]);
            acc[0][1] = fmaf(a0, bv.y, acc[0][1]);
            acc[0][2] = fmaf(a0, bv.z, acc[0][2]);
            acc[0][3] = fmaf(a0, bv.w, acc[0][3]);
            acc[1][0] = fmaf(a1, bv.x, acc[1][0]);
            acc[1][1] = fmaf(a1, bv.y, acc[1][1]);
            acc[1][2] = fmaf(a1, bv.z, acc[1][2]);
            acc[1][3] = fmaf(a1, bv.w, acc[1][3]);
            acc[2][0] = fmaf(a2, bv.x, acc[2][0]);
            acc[2][1] = fmaf(a2, bv.y, acc[2][1]);
            acc[2][2] = fmaf(a2, bv.z, acc[2][2]);
            acc[2][3] = fmaf(a2, bv.w, acc[2][3]);
            acc[3][0] = fmaf(a3, bv.x, acc[3][0]);
            acc[3][1] = fmaf(a3, bv.y, acc[3][1]);
            acc[3][2] = fmaf(a3, bv.z, acc[3][2]);
            acc[3][3] = fmaf(a3, bv.w, acc[3][3]);
        }
        #pragma unroll
        for (int q = 0; q < 4; q++) {
            int row = ti * 64 + 4 * ty + q;
            float4 o = make_float4(acc[q][0], acc[q][1], acc[q][2], acc[q][3]);
            *(float4*)&gout[(size_t)row * n + tj * 64 + 4 * tx] = o;
        }
    } else if (b < lab_block) {
        int r0 = (b - dist_blocks) * 32;
        #pragma unroll
        for (int it = 0; it < 4; it++) {
            int row = r0 + wid + it * 8;
            float4 v = e4[(size_t)row * 32 + lane];
            float s = v.x * v.x + v.y * v.y + v.z * v.z + v.w * v.w;
            #pragma unroll
            for (int off = 16; off; off >>= 1)
                s += __shfl_down_sync(0xFFFFFFFFu, s, off);
            if (lane == 0) g_sq[row] = s;
        }
    } else if (b == lab_block) {
        if (tid == 0) s_is64 = 1;
        __syncthreads();
        for (int idx = tid; idx < n / 2; idx += 256)
            if (lab32[2 * idx + 1] != 0) atomicExch(&s_is64, 0);
        __syncthreads();
        const bool is64 = (s_is64 != 0);
        for (int i2 = tid; i2 < n; i2 += 256)
            g_lab[i2] = is64 ? lab32[2 * i2] : lab32[i2];
    }

    // ================= grid barrier =================
    __threadfence();
    __syncthreads();
    if (tid == 0) {
        atomicAdd(&g_bar1, 1);
        volatile int* vb = &g_bar1;
        while (*vb < GRID) { __nanosleep(32); }
    }
    __syncthreads();

    // ================= phase 2: anchors via counting sort =================
    float lsum = 0.f;
    int   lcnt = 0;
    int   vtot = 0;

    for (int i = b; i < n; i += GRID) {
        const int   li  = g_lab[i];
        const float sqi = g_sq[i];
        const float* __restrict__ dA = &g_dotA[(size_t)i * n];
        const float* __restrict__ dB = &g_dotB[(size_t)i * n];

        __syncthreads();                 // prev anchor's structures fully consumed
        hcnt[tid] = 0;
        __syncthreads();

        // classify this thread's j slots; negatives -> histogram
        float dvs[3];
        int   typ[3];                    // 0 = neg, 1 = pos, 2 = skip
        #pragma unroll
        for (int s = 0; s < 3; s++) {
            int j = tid + s * 256;
            typ[s] = 2; dvs[s] = 0.f;
            if (j < n) {
                float dot = dA[j] + dB[j];
                float dv = sqrtf(fmaxf(sqi + g_sq[j] - 2.0f * dot, 0.0f));
                dvs[s] = dv;
                if (g_lab[j] == li) {
                    typ[s] = (j == i) ? 2 : 1;
                } else {
                    typ[s] = 0;
                    int bb = min(255, (int)(dv * BSCALE));
                    atomicAdd(&hcnt[bb], 1);
                }
            }
        }
        __syncthreads();

        // exclusive scan of counts -> pcs, cursors
        int vcnt = hcnt[tid];
        int inc = vcnt;
        #pragma unroll
        for (int off = 1; off < 32; off <<= 1) {
            int t = __shfl_up_sync(0xFFFFFFFFu, inc, off);
            if (lane >= off) inc += t;
        }
        if (lane == 31) swi[wid] = inc;
        __syncthreads();
        if (tid < 8) {
            int o = 0;
            for (int k = 0; k < tid; k++) o += swi[k];
            swi2[tid] = o;
        }
        __syncthreads();
        int exc = inc - vcnt + swi2[wid];
        pcs[tid] = exc;
        cur[tid] = exc;
        if (tid == 255) pcs[256] = exc + vcnt;
        __syncthreads();

        // scatter negatives grouped by bucket
        #pragma unroll
        for (int s = 0; s < 3; s++) {
            if (typ[s] == 0) {
                int bb = min(255, (int)(dvs[s] * BSCALE));
                int slot = atomicAdd(&cur[bb], 1);
                bval[slot] = dvs[s];
            }
        }
        __syncthreads();

        // per-bucket value sums -> exclusive scan pvs
        float sv = 0.f;
        {
            int s0 = pcs[tid], s1 = pcs[tid + 1];
            for (int k = s0; k < s1; k++) sv += bval[k];
        }
        float fin = sv;
        #pragma unroll
        for (int off = 1; off < 32; off <<= 1) {
            float t = __shfl_up_sync(0xFFFFFFFFu, fin, off);
            if (lane >= off) fin += t;
        }
        if (lane == 31) swf[wid] = fin;
        __syncthreads();
        if (tid < 8) {
            float o = 0.f;
            for (int k = 0; k < tid; k++) o += swf[k];
            swf2[tid] = o;
        }
        __syncthreads();
        pvs[tid] = fin - sv + swf2[wid];
        __syncthreads();

        // positives: O(1) prefix lookup + boundary-bucket exact scan
        const int Ntot = pcs[256];
        #pragma unroll
        for (int s = 0; s < 3; s++) {
            if (typ[s] == 1) {
                float t = dvs[s] + MARGIN;
                int bb = min(255, (int)(t * BSCALE));
                int cnt = pcs[bb];
                float sm = pvs[bb];
                int e1 = pcs[bb + 1];
                for (int k = pcs[bb]; k < e1; k++) {
                    float vv = bval[k];
                    if (vv < t) { cnt++; sm += vv; }
                }
                lcnt += cnt;
                lsum += (float)cnt * t - sm;
            }
        }
        vtot += (n - 1 - Ntot) * Ntot;   // P = n-1-Ntot; identical on all threads
    }

    // block reduce (lsum, lcnt)
    #pragma unroll
    for (int off = 16; off; off >>= 1) {
        lsum += __shfl_down_sync(0xFFFFFFFFu, lsum, off);
        lcnt += __shfl_down_sync(0xFFFFFFFFu, lcnt, off);
    }
    if (lane == 0) { wsum[wid] = lsum; wcnt[wid] = lcnt; }
    __syncthreads();
    if (tid == 0) {
        float s = 0.f; int c = 0;
        #pragma unroll
        for (int w = 0; w < 8; w++) { s += wsum[w]; c += wcnt[w]; }
        g_bsum[b] = s;
        g_bcnt[b] = c;
        g_bval[b] = vtot;
    }

    // ================= phase 3: last block finalizes =================
    __threadfence();
    __syncthreads();
    if (tid == 0) s_old = atomicAdd(&g_bar2, 1);
    __syncthreads();
    if (s_old == GRID - 1) {
        float s = 0.f; int c = 0, v = 0;
        for (int idx = tid; idx < GRID; idx += 256) {
            s += g_bsum[idx];
            c += g_bcnt[idx];
            v += g_bval[idx];
        }
        #pragma unroll
        for (int off = 16; off; off >>= 1) {
            s += __shfl_down_sync(0xFFFFFFFFu, s, off);
            c += __shfl_down_sync(0xFFFFFFFFu, c, off);
            v += __shfl_down_sync(0xFFFFFFFFu, v, off);
        }
        __shared__ float fs[8];
        __shared__ int   fc[8], fv[8];
        if (lane == 0) { fs[wid] = s; fc[wid] = c; fv[wid] = v; }
        __syncthreads();
        if (tid == 0) {
            float total = 0.f; int cnt = 0, val = 0;
            #pragma unroll
            for (int w = 0; w < 8; w++) { total += fs[w]; cnt += fc[w]; val += fv[w]; }
            float num_non   = (float)cnt;
            float num_valid = (float)val;
            out[0] = (cnt > 0) ? total / fmaxf(num_non, 1.0f) : 0.0f;
            out[1] = num_valid;
            out[2] = num_non;
            out[3] = num_non / (num_valid + 1e-16f);
            g_bar1 = 0;
            g_bar2 = 0;
            __threadfence();
        }
    }
}

extern "C" void kernel_launch(void* const* d_in, const int* in_sizes, int n_in,
                              void* d_out, int out_size) {
    const float* e   = (const float*)d_in[0];   // embeddings [8,80,128] fp32
    const int*   lab = (const int*)d_in[1];     // labels (int64 or int32 view)
    int n = in_sizes[1];                        // 640

    fused_triplet_kernel<<<GRID, 256>>>(e, lab, (float*)d_out, n);
}